// round 2
// baseline (speedup 1.0000x reference)
#include <cuda_runtime.h>

#define SQ 1024
#define HD 64
#define TQ 128
#define CK 128
#define NCHUNK (SQ / CK)
#define NTHREADS 256

// smem pitches (floats). A-side tiles: pitch % 32 == 4 (banks = 4*gID + tig, all distinct).
// B-side tiles: pitch % 32 == 8 (banks = 8*tig + gID, all distinct).
#define QP 68
#define KP 136
#define WP 132
#define VP 72

// smem float offsets
#define OFF_QS 0        // phase1: 128 x 68  = 8704
#define OFF_KS 8704     // phase1: 64 x 136  = 8704  (ends 17408)
#define OFF_WS 0        // phase2: 128 x 132 = 16896
#define OFF_VS 16896    // phase2: 128 x 72  = 9216  (ends 26112)
#define OFF_RS 26112    // rowsum: 2 x 128
#define OFF_INV 26368   // invs: 128
#define SMEM_FLOATS 26496

__device__ __forceinline__ unsigned f2tf32(float v) {
    unsigned r;
    asm("cvt.rna.tf32.f32 %0, %1;" : "=r"(r) : "f"(v));
    return r;
}
__device__ __forceinline__ float tf32f(float v) { return __uint_as_float(f2tf32(v)); }

__device__ __forceinline__ void mma16x8x8(float* c, const unsigned* a, const unsigned* b) {
    asm volatile(
        "mma.sync.aligned.m16n8k8.row.col.f32.tf32.tf32.f32 "
        "{%0,%1,%2,%3}, {%4,%5,%6,%7}, {%8,%9}, {%0,%1,%2,%3};\n"
        : "+f"(c[0]), "+f"(c[1]), "+f"(c[2]), "+f"(c[3])
        : "r"(a[0]), "r"(a[1]), "r"(a[2]), "r"(a[3]),
          "r"(b[0]), "r"(b[1]));
}

__global__ __launch_bounds__(NTHREADS, 2)
void attn_fused2_kernel(const float* __restrict__ q, const float* __restrict__ k,
                        const float* __restrict__ v, const float* __restrict__ prev,
                        const float* __restrict__ mask, const float* __restrict__ scale_p,
                        float* __restrict__ out, float* __restrict__ wts,
                        float* __restrict__ scr)
{
    extern __shared__ float smem[];
    float* Qs = smem + OFF_QS;
    float* Ks = smem + OFF_KS;
    float* Ws = smem + OFF_WS;
    float* Vs = smem + OFF_VS;
    float* rowsum = smem + OFF_RS;
    float* invs = smem + OFF_INV;

    const int bh  = blockIdx.y;
    const int q0  = blockIdx.x * TQ;
    const int tid = threadIdx.x;
    const int wid = tid >> 5;
    const int lane = tid & 31;
    const int gID = lane >> 2;       // 0..7
    const int tig = lane & 3;        // 0..3
    const int wm  = wid & 3;         // M-split 0..3 (32 rows each)
    const int wn  = wid >> 2;        // N-split 0..1
    const int rbase = wm * 32;

    const float scale = __ldg(scale_p);

    const float* qh = q    + (size_t)bh * SQ * HD;
    const float* kh = k    + (size_t)bh * HD * SQ;   // [D][S]
    const float* vh = v    + (size_t)bh * SQ * HD;
    const float* ph = prev + (size_t)bh * SQ * SQ;
    float* outh = out + (size_t)bh * SQ * HD;
    float* wh   = wts + (size_t)bh * SQ * SQ;
    float* shh  = scr + (size_t)bh * SQ * SQ;

    // ---- Q tile -> smem (tf32) ----
    for (int i = tid; i < TQ * (HD / 4); i += NTHREADS) {
        int r = i >> 4;
        int c4 = (i & 15) << 2;
        float4 t = *(const float4*)(qh + (size_t)(q0 + r) * HD + c4);
        float* dst = Qs + r * QP + c4;
        dst[0] = tf32f(t.x); dst[1] = tf32f(t.y);
        dst[2] = tf32f(t.z); dst[3] = tf32f(t.w);
    }

    float ls[2][2] = {{0.f, 0.f}, {0.f, 0.f}};

    // =================== Phase 1: scores + row exp-sums ===================
    for (int ch = 0; ch < NCHUNK; ch++) {
        const int s0 = ch * CK;
        __syncthreads();
        for (int i = tid; i < HD * (CK / 4); i += NTHREADS) {
            int r = i >> 5;
            int c4 = (i & 31) << 2;
            float4 t = *(const float4*)(kh + (size_t)r * SQ + s0 + c4);
            float* dst = Ks + r * KP + c4;
            dst[0] = tf32f(t.x); dst[1] = tf32f(t.y);
            dst[2] = tf32f(t.z); dst[3] = tf32f(t.w);
        }
        __syncthreads();

        float acc[2][8][4];
        #pragma unroll
        for (int m = 0; m < 2; m++)
            #pragma unroll
            for (int n = 0; n < 8; n++) {
                acc[m][n][0] = 0.f; acc[m][n][1] = 0.f;
                acc[m][n][2] = 0.f; acc[m][n][3] = 0.f;
            }

        #pragma unroll
        for (int kk = 0; kk < 8; kk++) {
            const int d0 = kk * 8;
            unsigned a[2][4];
            #pragma unroll
            for (int m = 0; m < 2; m++) {
                const int rr = rbase + m * 16 + gID;
                a[m][0] = __float_as_uint(Qs[rr * QP + d0 + tig]);
                a[m][1] = __float_as_uint(Qs[(rr + 8) * QP + d0 + tig]);
                a[m][2] = __float_as_uint(Qs[rr * QP + d0 + tig + 4]);
                a[m][3] = __float_as_uint(Qs[(rr + 8) * QP + d0 + tig + 4]);
            }
            #pragma unroll
            for (int n = 0; n < 8; n++) {
                const int col = wn * 64 + n * 8 + gID;
                unsigned b[2];
                b[0] = __float_as_uint(Ks[(d0 + tig) * KP + col]);
                b[1] = __float_as_uint(Ks[(d0 + tig + 4) * KP + col]);
                mma16x8x8(acc[0][n], a[0], b);
                mma16x8x8(acc[1][n], a[1], b);
            }
        }

        // epilogue: s = qk*mask*scale + prev; store scores; accumulate exp-sums
        #pragma unroll
        for (int m = 0; m < 2; m++) {
            const int gr0 = q0 + rbase + m * 16 + gID;
            const int gr1 = gr0 + 8;
            #pragma unroll
            for (int n = 0; n < 8; n++) {
                const int col = s0 + wn * 64 + n * 8 + tig * 2;
                float2 m0 = *(const float2*)(mask + (size_t)gr0 * SQ + col);
                float2 m1 = *(const float2*)(mask + (size_t)gr1 * SQ + col);
                float2 p0 = *(const float2*)(ph   + (size_t)gr0 * SQ + col);
                float2 p1 = *(const float2*)(ph   + (size_t)gr1 * SQ + col);
                float s00 = acc[m][n][0] * m0.x * scale + p0.x;
                float s01 = acc[m][n][1] * m0.y * scale + p0.y;
                float s10 = acc[m][n][2] * m1.x * scale + p1.x;
                float s11 = acc[m][n][3] * m1.y * scale + p1.y;
                *(float2*)(shh + (size_t)gr0 * SQ + col) = make_float2(s00, s01);
                *(float2*)(shh + (size_t)gr1 * SQ + col) = make_float2(s10, s11);
                ls[m][0] += __expf(s00) + __expf(s01);
                ls[m][1] += __expf(s10) + __expf(s11);
            }
        }
    }

    // reduce over tig lanes, then across the 2 N-split warps via smem
    #pragma unroll
    for (int m = 0; m < 2; m++)
        #pragma unroll
        for (int j = 0; j < 2; j++) {
            ls[m][j] += __shfl_xor_sync(0xffffffffu, ls[m][j], 1);
            ls[m][j] += __shfl_xor_sync(0xffffffffu, ls[m][j], 2);
        }
    if (tig == 0) {
        #pragma unroll
        for (int m = 0; m < 2; m++)
            #pragma unroll
            for (int j = 0; j < 2; j++)
                rowsum[wn * 128 + rbase + m * 16 + j * 8 + gID] = ls[m][j];
    }
    __syncthreads();
    if (tid < 128) invs[tid] = 1.0f / (rowsum[tid] + rowsum[128 + tid]);

    // =================== Phase 2: weights + output = W @ V ===================
    float oacc[2][4][4];
    #pragma unroll
    for (int m = 0; m < 2; m++)
        #pragma unroll
        for (int n = 0; n < 4; n++) {
            oacc[m][n][0] = 0.f; oacc[m][n][1] = 0.f;
            oacc[m][n][2] = 0.f; oacc[m][n][3] = 0.f;
        }

    for (int ch = 0; ch < NCHUNK; ch++) {
        const int s0 = ch * CK;
        __syncthreads();

        // stage: scores -> weights (gmem, float4) + tf32 weights -> smem
        for (int i = tid; i < TQ * (CK / 4); i += NTHREADS) {
            int r = i >> 5;
            int c4 = (i & 31) << 2;
            float4 s = *(const float4*)(shh + (size_t)(q0 + r) * SQ + s0 + c4);
            const float iv = invs[r];
            float4 w;
            w.x = __expf(s.x) * iv; w.y = __expf(s.y) * iv;
            w.z = __expf(s.z) * iv; w.w = __expf(s.w) * iv;
            *(float4*)(wh + (size_t)(q0 + r) * SQ + s0 + c4) = w;
            float* dst = Ws + r * WP + c4;
            dst[0] = tf32f(w.x); dst[1] = tf32f(w.y);
            dst[2] = tf32f(w.z); dst[3] = tf32f(w.w);
        }
        // V chunk -> smem (tf32)
        for (int i = tid; i < CK * (HD / 4); i += NTHREADS) {
            int r = i >> 4;
            int c4 = (i & 15) << 2;
            float4 t = *(const float4*)(vh + (size_t)(s0 + r) * HD + c4);
            float* dst = Vs + r * VP + c4;
            dst[0] = tf32f(t.x); dst[1] = tf32f(t.y);
            dst[2] = tf32f(t.z); dst[3] = tf32f(t.w);
        }
        __syncthreads();

        #pragma unroll
        for (int kk = 0; kk < 16; kk++) {
            const int k0 = kk * 8;
            unsigned a[2][4];
            #pragma unroll
            for (int m = 0; m < 2; m++) {
                const int rr = rbase + m * 16 + gID;
                a[m][0] = __float_as_uint(Ws[rr * WP + k0 + tig]);
                a[m][1] = __float_as_uint(Ws[(rr + 8) * WP + k0 + tig]);
                a[m][2] = __float_as_uint(Ws[rr * WP + k0 + tig + 4]);
                a[m][3] = __float_as_uint(Ws[(rr + 8) * WP + k0 + tig + 4]);
            }
            #pragma unroll
            for (int n = 0; n < 4; n++) {
                const int col = wn * 32 + n * 8 + gID;
                unsigned b[2];
                b[0] = __float_as_uint(Vs[(k0 + tig) * VP + col]);
                b[1] = __float_as_uint(Vs[(k0 + tig + 4) * VP + col]);
                mma16x8x8(oacc[0][n], a[0], b);
                mma16x8x8(oacc[1][n], a[1], b);
            }
        }
    }

    // write output tile
    #pragma unroll
    for (int m = 0; m < 2; m++) {
        const int gr0 = q0 + rbase + m * 16 + gID;
        const int gr1 = gr0 + 8;
        #pragma unroll
        for (int n = 0; n < 4; n++) {
            const int col = wn * 32 + n * 8 + tig * 2;
            *(float2*)(outh + (size_t)gr0 * HD + col) = make_float2(oacc[m][n][0], oacc[m][n][1]);
            *(float2*)(outh + (size_t)gr1 * HD + col) = make_float2(oacc[m][n][2], oacc[m][n][3]);
        }
    }
}

extern "C" void kernel_launch(void* const* d_in, const int* in_sizes, int n_in,
                              void* d_out, int out_size) {
    const float* q     = (const float*)d_in[0];
    const float* k     = (const float*)d_in[1];
    const float* v     = (const float*)d_in[2];
    const float* prev  = (const float*)d_in[3];
    const float* mask  = (const float*)d_in[4];
    const float* scale = (const float*)d_in[5];

    float* out = (float*)d_out;
    float* wts = out + (size_t)8 * 16 * 1024 * 64;
    float* scr = wts + (size_t)8 * 16 * 1024 * 1024;

    const size_t smem_bytes = (size_t)SMEM_FLOATS * sizeof(float);
    cudaFuncSetAttribute(attn_fused2_kernel,
                         cudaFuncAttributeMaxDynamicSharedMemorySize, (int)smem_bytes);

    dim3 grid(SQ / TQ, 8 * 16);
    attn_fused2_kernel<<<grid, NTHREADS, smem_bytes>>>(q, k, v, prev, mask, scale,
                                                       out, wts, scr);
}

// round 3
// speedup vs baseline: 1.1059x; 1.1059x over previous
#include <cuda_runtime.h>

#define SQ 1024
#define HD 64
#define TQ 64          // query rows per CTA
#define CK 64          // key cols per chunk
#define NCH (SQ / CK)  // 16
#define NTHREADS 256

// pitches (floats): A-side (Qs, Es) % 32 == 4 ; B-side (Ks, Vs) % 32 == 8
#define QP 68
#define KP 72
#define VP 72
#define EP 68

// smem float offsets
#define OFF_QS 0                      // 64 x 68 = 4352
#define OFF_KS 4352                   // 64 x 72 = 4608
#define OFF_VS (4352 + 4608)          // 64 x 72 = 4608
#define OFF_ES (4352 + 4608 + 4608)   // 64 x 68 = 4352
#define OFF_RS (OFF_ES + 4352)        // 2 x 64
#define OFF_INV (OFF_RS + 128)        // 64
#define SMEM_FLOATS (OFF_INV + 64)    // 18112 floats = 72448 B

__device__ __forceinline__ unsigned f2tf32(float v) {
    unsigned r;
    asm("cvt.rna.tf32.f32 %0, %1;" : "=r"(r) : "f"(v));
    return r;
}
__device__ __forceinline__ float tf32f(float v) { return __uint_as_float(f2tf32(v)); }

__device__ __forceinline__ void mma16x8x8(float* c, const unsigned* a, const unsigned* b) {
    asm volatile(
        "mma.sync.aligned.m16n8k8.row.col.f32.tf32.tf32.f32 "
        "{%0,%1,%2,%3}, {%4,%5,%6,%7}, {%8,%9}, {%0,%1,%2,%3};\n"
        : "+f"(c[0]), "+f"(c[1]), "+f"(c[2]), "+f"(c[3])
        : "r"(a[0]), "r"(a[1]), "r"(a[2]), "r"(a[3]),
          "r"(b[0]), "r"(b[1]));
}

__global__ __launch_bounds__(NTHREADS, 3)
void attn_fa_kernel(const float* __restrict__ q, const float* __restrict__ k,
                    const float* __restrict__ v, const float* __restrict__ prev,
                    const float* __restrict__ mask, const float* __restrict__ scale_p,
                    float* __restrict__ out, float* __restrict__ wts,
                    float* __restrict__ scr)
{
    extern __shared__ float smem[];
    float* Qs = smem + OFF_QS;
    float* Ks = smem + OFF_KS;
    float* Vs = smem + OFF_VS;
    float* Es = smem + OFF_ES;
    float* rowsum = smem + OFF_RS;
    float* invs = smem + OFF_INV;

    const int bh  = blockIdx.y;
    const int q0  = blockIdx.x * TQ;
    const int tid = threadIdx.x;
    const int wid = tid >> 5;
    const int lane = tid & 31;
    const int gID = lane >> 2;       // 0..7
    const int tig = lane & 3;        // 0..3
    const int wm  = wid & 3;         // 4-way M split (16 rows each)
    const int wn  = wid >> 2;        // 2-way N split (32 cols each)
    const int r0  = wm * 16 + gID;
    const int r1  = r0 + 8;
    const int gr0 = q0 + r0;
    const int gr1 = q0 + r1;

    const float scale = __ldg(scale_p);

    const float* qh = q    + (size_t)bh * SQ * HD;
    const float* kh = k    + (size_t)bh * HD * SQ;   // [D][S]
    const float* vh = v    + (size_t)bh * SQ * HD;
    const float* ph = prev + (size_t)bh * SQ * SQ;
    float* outh = out + (size_t)bh * SQ * HD;
    float* wh   = wts + (size_t)bh * SQ * SQ;
    float* shh  = scr + (size_t)bh * SQ * SQ;

    // ---- Q tile -> smem (tf32) : 64x64, 4 float4 per thread ----
    #pragma unroll
    for (int ii = 0; ii < 4; ii++) {
        int i = tid + ii * NTHREADS;
        int r = i >> 4;
        int c4 = (i & 15) << 2;
        float4 t = *(const float4*)(qh + (size_t)(q0 + r) * HD + c4);
        float* dst = Qs + r * QP + c4;
        dst[0] = tf32f(t.x); dst[1] = tf32f(t.y);
        dst[2] = tf32f(t.z); dst[3] = tf32f(t.w);
    }

    float oacc[4][4];
    #pragma unroll
    for (int n = 0; n < 4; n++) {
        oacc[n][0] = 0.f; oacc[n][1] = 0.f; oacc[n][2] = 0.f; oacc[n][3] = 0.f;
    }
    float ls0 = 0.f, ls1 = 0.f;

    for (int ch = 0; ch < NCH; ch++) {
        const int s0 = ch * CK;
        __syncthreads();   // prior chunk mma1/mma2 done -> safe to overwrite Ks/Vs/Es
        // K chunk [HD][CK] and V chunk [CK][HD], tf32 into smem
        #pragma unroll
        for (int ii = 0; ii < 4; ii++) {
            int i = tid + ii * NTHREADS;
            int r = i >> 4;
            int c4 = (i & 15) << 2;
            float4 t = *(const float4*)(kh + (size_t)r * SQ + s0 + c4);
            float* dst = Ks + r * KP + c4;
            dst[0] = tf32f(t.x); dst[1] = tf32f(t.y);
            dst[2] = tf32f(t.z); dst[3] = tf32f(t.w);
        }
        #pragma unroll
        for (int ii = 0; ii < 4; ii++) {
            int i = tid + ii * NTHREADS;
            int r = i >> 4;
            int c4 = (i & 15) << 2;
            float4 t = *(const float4*)(vh + (size_t)(s0 + r) * HD + c4);
            float* dst = Vs + r * VP + c4;
            dst[0] = tf32f(t.x); dst[1] = tf32f(t.y);
            dst[2] = tf32f(t.z); dst[3] = tf32f(t.w);
        }
        __syncthreads();

        // ---- mma1: S = Q @ K  (per-warp 16x32) ----
        float acc[4][4];
        #pragma unroll
        for (int n = 0; n < 4; n++) {
            acc[n][0] = 0.f; acc[n][1] = 0.f; acc[n][2] = 0.f; acc[n][3] = 0.f;
        }
        #pragma unroll
        for (int kk = 0; kk < 8; kk++) {
            const int d0 = kk * 8;
            unsigned a[4];
            a[0] = __float_as_uint(Qs[r0 * QP + d0 + tig]);
            a[1] = __float_as_uint(Qs[r1 * QP + d0 + tig]);
            a[2] = __float_as_uint(Qs[r0 * QP + d0 + tig + 4]);
            a[3] = __float_as_uint(Qs[r1 * QP + d0 + tig + 4]);
            #pragma unroll
            for (int n = 0; n < 4; n++) {
                const int col = wn * 32 + n * 8 + gID;
                unsigned b[2];
                b[0] = __float_as_uint(Ks[(d0 + tig) * KP + col]);
                b[1] = __float_as_uint(Ks[(d0 + tig + 4) * KP + col]);
                mma16x8x8(acc[n], a, b);
            }
        }

        // ---- epilogue: scores out, exp to smem, rowsum accumulate ----
        #pragma unroll
        for (int n = 0; n < 4; n++) {
            const int lc  = wn * 32 + n * 8 + tig * 2;   // col within chunk
            const int col = s0 + lc;
            float2 m0 = *(const float2*)(mask + (size_t)gr0 * SQ + col);
            float2 m1 = *(const float2*)(mask + (size_t)gr1 * SQ + col);
            float2 p0 = *(const float2*)(ph   + (size_t)gr0 * SQ + col);
            float2 p1 = *(const float2*)(ph   + (size_t)gr1 * SQ + col);
            float s00 = acc[n][0] * m0.x * scale + p0.x;
            float s01 = acc[n][1] * m0.y * scale + p0.y;
            float s10 = acc[n][2] * m1.x * scale + p1.x;
            float s11 = acc[n][3] * m1.y * scale + p1.y;
            *(float2*)(shh + (size_t)gr0 * SQ + col) = make_float2(s00, s01);
            *(float2*)(shh + (size_t)gr1 * SQ + col) = make_float2(s10, s11);
            float e00 = __expf(s00), e01 = __expf(s01);
            float e10 = __expf(s10), e11 = __expf(s11);
            ls0 += e00 + e01;
            ls1 += e10 + e11;
            *(float2*)(Es + r0 * EP + lc) = make_float2(tf32f(e00), tf32f(e01));
            *(float2*)(Es + r1 * EP + lc) = make_float2(tf32f(e10), tf32f(e11));
        }
        __syncthreads();   // Es complete (cross-warp A-fragments)

        // ---- mma2: out_unnorm += exp(S) @ V  (per-warp 16x32) ----
        #pragma unroll
        for (int kk = 0; kk < 8; kk++) {
            const int k0 = kk * 8;
            unsigned a[4];
            a[0] = __float_as_uint(Es[r0 * EP + k0 + tig]);
            a[1] = __float_as_uint(Es[r1 * EP + k0 + tig]);
            a[2] = __float_as_uint(Es[r0 * EP + k0 + tig + 4]);
            a[3] = __float_as_uint(Es[r1 * EP + k0 + tig + 4]);
            #pragma unroll
            for (int n = 0; n < 4; n++) {
                const int oc = wn * 32 + n * 8 + gID;
                unsigned b[2];
                b[0] = __float_as_uint(Vs[(k0 + tig) * VP + oc]);
                b[1] = __float_as_uint(Vs[(k0 + tig + 4) * VP + oc]);
                mma16x8x8(oacc[n], a, b);
            }
        }
    }

    // ---- rowsums -> invs ----
    ls0 += __shfl_xor_sync(0xffffffffu, ls0, 1);
    ls0 += __shfl_xor_sync(0xffffffffu, ls0, 2);
    ls1 += __shfl_xor_sync(0xffffffffu, ls1, 1);
    ls1 += __shfl_xor_sync(0xffffffffu, ls1, 2);
    if (tig == 0) {
        rowsum[wn * 64 + r0] = ls0;
        rowsum[wn * 64 + r1] = ls1;
    }
    __syncthreads();
    if (tid < TQ) invs[tid] = 1.0f / (rowsum[tid] + rowsum[64 + tid]);
    __syncthreads();

    // ---- write output (normalized) ----
    {
        const float inv0 = invs[r0];
        const float inv1 = invs[r1];
        #pragma unroll
        for (int n = 0; n < 4; n++) {
            const int col = wn * 32 + n * 8 + tig * 2;
            *(float2*)(outh + (size_t)gr0 * HD + col) =
                make_float2(oacc[n][0] * inv0, oacc[n][1] * inv0);
            *(float2*)(outh + (size_t)gr1 * HD + col) =
                make_float2(oacc[n][2] * inv1, oacc[n][3] * inv1);
        }
    }

    // ---- weights tail: w = exp(score) * inv  (coalesced float4 streaming) ----
    #pragma unroll 4
    for (int i = tid; i < TQ * (SQ / 4); i += NTHREADS) {
        int r  = i >> 8;                 // 256 float4 per row
        int c4 = (i & 255) << 2;
        const float iv = invs[r];
        float4 s = *(const float4*)(shh + (size_t)(q0 + r) * SQ + c4);
        float4 w;
        w.x = __expf(s.x) * iv; w.y = __expf(s.y) * iv;
        w.z = __expf(s.z) * iv; w.w = __expf(s.w) * iv;
        *(float4*)(wh + (size_t)(q0 + r) * SQ + c4) = w;
    }
}

extern "C" void kernel_launch(void* const* d_in, const int* in_sizes, int n_in,
                              void* d_out, int out_size) {
    const float* q     = (const float*)d_in[0];
    const float* k     = (const float*)d_in[1];
    const float* v     = (const float*)d_in[2];
    const float* prev  = (const float*)d_in[3];
    const float* mask  = (const float*)d_in[4];
    const float* scale = (const float*)d_in[5];

    float* out = (float*)d_out;
    float* wts = out + (size_t)8 * 16 * 1024 * 64;
    float* scr = wts + (size_t)8 * 16 * 1024 * 1024;

    const size_t smem_bytes = (size_t)SMEM_FLOATS * sizeof(float);
    cudaFuncSetAttribute(attn_fa_kernel,
                         cudaFuncAttributeMaxDynamicSharedMemorySize, (int)smem_bytes);

    dim3 grid(SQ / TQ, 8 * 16);   // (16 q-tiles, 128 bh)
    attn_fa_kernel<<<grid, NTHREADS, smem_bytes>>>(q, k, v, prev, mask, scale,
                                                   out, wts, scr);
}

// round 4
// speedup vs baseline: 1.3532x; 1.2236x over previous
#include <cuda_runtime.h>
#include <cstdint>

#define SQ 1024
#define HD 64
#define TQ 64          // query rows per CTA
#define CK 32          // key cols per chunk
#define NCH (SQ / CK)  // 32
#define NTHREADS 256

// pitches (floats): A-side %32==4, B-side %32==8; rows must be 16B-aligned for cp.async
#define QP 68          // Q  [64][64]  A-side
#define KP 40          // K  [64][32]  B-side
#define VP 72          // V  [32][64]  B-side
#define PP 36          // prev/exp [64][32] A-side

// smem float offsets
#define OFF_QS 0                     // 64*68           = 4352
#define OFF_KS 4352                  // 2 * 64*40       = 5120
#define OFF_VS (4352+5120)           // 2 * 32*72       = 4608
#define OFF_PS (4352+5120+4608)      // 2 * 64*36       = 4608
#define OFF_RS (OFF_PS+4608)         // 128
#define OFF_INV (OFF_RS+128)         // 64
#define SMEM_FLOATS (OFF_INV+64)     // 18880 floats = 75520 B

#define KBUF 2560                    // 64*40
#define VBUF 2304                    // 32*72
#define PBUF 2304                    // 64*36

__device__ __forceinline__ unsigned f2tf32(float v) {
    unsigned r;
    asm("cvt.rna.tf32.f32 %0, %1;" : "=r"(r) : "f"(v));
    return r;
}

__device__ __forceinline__ void mma16x8x8(float* c, const unsigned* a, const unsigned* b) {
    asm volatile(
        "mma.sync.aligned.m16n8k8.row.col.f32.tf32.tf32.f32 "
        "{%0,%1,%2,%3}, {%4,%5,%6,%7}, {%8,%9}, {%0,%1,%2,%3};\n"
        : "+f"(c[0]), "+f"(c[1]), "+f"(c[2]), "+f"(c[3])
        : "r"(a[0]), "r"(a[1]), "r"(a[2]), "r"(a[3]),
          "r"(b[0]), "r"(b[1]));
}

__device__ __forceinline__ void cp16(uint32_t dst, const void* src) {
    asm volatile("cp.async.cg.shared.global [%0], [%1], 16;" :: "r"(dst), "l"(src));
}
__device__ __forceinline__ void cp_commit() {
    asm volatile("cp.async.commit_group;" ::: "memory");
}
template<int N> __device__ __forceinline__ void cp_wait() {
    asm volatile("cp.async.wait_group %0;" :: "n"(N) : "memory");
}

__global__ __launch_bounds__(NTHREADS, 3)
void attn_pipe_kernel(const float* __restrict__ q, const float* __restrict__ k,
                      const float* __restrict__ v, const float* __restrict__ prev,
                      const float* __restrict__ mask, const float* __restrict__ scale_p,
                      float* __restrict__ out, float* __restrict__ wts,
                      float* __restrict__ scr)
{
    extern __shared__ float smem[];
    const uint32_t sbase = (uint32_t)__cvta_generic_to_shared(smem);
    float* Qs = smem + OFF_QS;
    float* rowsum = smem + OFF_RS;
    float* invs = smem + OFF_INV;

    const int bh  = blockIdx.y;
    const int q0  = blockIdx.x * TQ;
    const int tid = threadIdx.x;
    const int wid = tid >> 5;
    const int lane = tid & 31;
    const int gID = lane >> 2;       // 0..7
    const int tig = lane & 3;        // 0..3
    const int wm  = wid & 3;         // 4-way M split (16 rows)
    const int wn  = wid >> 2;        // 2-way N split (16 cols of CK=32)
    const int r0  = wm * 16 + gID;
    const int r1  = r0 + 8;
    const int gr0 = q0 + r0;
    const int gr1 = q0 + r1;

    const float scale = __ldg(scale_p);

    const float* qh = q    + (size_t)bh * SQ * HD;
    const float* kh = k    + (size_t)bh * HD * SQ;   // [D][S]
    const float* vh = v    + (size_t)bh * SQ * HD;
    const float* ph = prev + (size_t)bh * SQ * SQ;
    float* outh = out + (size_t)bh * SQ * HD;
    float* wh   = wts + (size_t)bh * SQ * SQ;
    float* shh  = scr + (size_t)bh * SQ * SQ;

    // ---- stage chunk ch into buffer buf (6 cp.async per thread) ----
    auto stage_chunk = [&](int ch, int buf) {
        const int s0 = ch * CK;
        // K [64 d][32 s]: 512 cp16
        {
            int i = tid;                     // j=0
            int r = i >> 3, c = (i & 7) << 2;
            cp16(sbase + (uint32_t)(OFF_KS + buf * KBUF + r * KP + c) * 4,
                 kh + (size_t)r * SQ + s0 + c);
            i += NTHREADS;
            r = i >> 3; c = (i & 7) << 2;
            cp16(sbase + (uint32_t)(OFF_KS + buf * KBUF + r * KP + c) * 4,
                 kh + (size_t)r * SQ + s0 + c);
        }
        // V [32 s][64 d]: 512 cp16
        {
            int i = tid;
            int r = i >> 4, c = (i & 15) << 2;
            cp16(sbase + (uint32_t)(OFF_VS + buf * VBUF + r * VP + c) * 4,
                 vh + (size_t)(s0 + r) * HD + c);
            i += NTHREADS;
            r = i >> 4; c = (i & 15) << 2;
            cp16(sbase + (uint32_t)(OFF_VS + buf * VBUF + r * VP + c) * 4,
                 vh + (size_t)(s0 + r) * HD + c);
        }
        // prev [64 q][32 s]: 512 cp16
        {
            int i = tid;
            int r = i >> 3, c = (i & 7) << 2;
            cp16(sbase + (uint32_t)(OFF_PS + buf * PBUF + r * PP + c) * 4,
                 ph + (size_t)(q0 + r) * SQ + s0 + c);
            i += NTHREADS;
            r = i >> 3; c = (i & 7) << 2;
            cp16(sbase + (uint32_t)(OFF_PS + buf * PBUF + r * PP + c) * 4,
                 ph + (size_t)(q0 + r) * SQ + s0 + c);
        }
    };

    // ---- group 0: Q tile + chunk 0 ----
    #pragma unroll
    for (int j = 0; j < 4; j++) {
        int i = tid + j * NTHREADS;
        int r = i >> 4, c = (i & 15) << 2;
        cp16(sbase + (uint32_t)(OFF_QS + r * QP + c) * 4,
             qh + (size_t)(q0 + r) * HD + c);
    }
    stage_chunk(0, 0);
    cp_commit();

    float oacc[4][4];
    #pragma unroll
    for (int n = 0; n < 4; n++) {
        oacc[n][0] = 0.f; oacc[n][1] = 0.f; oacc[n][2] = 0.f; oacc[n][3] = 0.f;
    }
    float ls0 = 0.f, ls1 = 0.f;

    for (int ch = 0; ch < NCH; ch++) {
        const int buf = ch & 1;
        const int s0 = ch * CK;
        float* Ks = smem + OFF_KS + buf * KBUF;
        float* Vs = smem + OFF_VS + buf * VBUF;
        float* Ps = smem + OFF_PS + buf * PBUF;   // prev in, exp out (same thread)

        if (ch + 1 < NCH) {
            stage_chunk(ch + 1, buf ^ 1);
            cp_commit();
            cp_wait<1>();
        } else {
            cp_wait<0>();
        }
        __syncthreads();

        // hoisted mask loads (L2-hot), consumed in epilogue
        float2 mk0[2], mk1[2];
        #pragma unroll
        for (int n = 0; n < 2; n++) {
            const int col = s0 + wn * 16 + n * 8 + tig * 2;
            mk0[n] = *(const float2*)(mask + (size_t)gr0 * SQ + col);
            mk1[n] = *(const float2*)(mask + (size_t)gr1 * SQ + col);
        }

        // ---- mma1: S = Q @ K (per-warp 16x16) ----
        float acc[2][4];
        #pragma unroll
        for (int n = 0; n < 2; n++) {
            acc[n][0] = 0.f; acc[n][1] = 0.f; acc[n][2] = 0.f; acc[n][3] = 0.f;
        }
        #pragma unroll
        for (int kk = 0; kk < 8; kk++) {
            const int d0 = kk * 8;
            unsigned a[4];
            a[0] = f2tf32(Qs[r0 * QP + d0 + tig]);
            a[1] = f2tf32(Qs[r1 * QP + d0 + tig]);
            a[2] = f2tf32(Qs[r0 * QP + d0 + tig + 4]);
            a[3] = f2tf32(Qs[r1 * QP + d0 + tig + 4]);
            #pragma unroll
            for (int n = 0; n < 2; n++) {
                const int col = wn * 16 + n * 8 + gID;
                unsigned b[2];
                b[0] = f2tf32(Ks[(d0 + tig) * KP + col]);
                b[1] = f2tf32(Ks[(d0 + tig + 4) * KP + col]);
                mma16x8x8(acc[n], a, b);
            }
        }

        // ---- epilogue: scores -> gmem, exp -> Ps (in place), rowsums ----
        #pragma unroll
        for (int n = 0; n < 2; n++) {
            const int lc  = wn * 16 + n * 8 + tig * 2;
            const int col = s0 + lc;
            float2 p0 = *(const float2*)(Ps + r0 * PP + lc);
            float2 p1 = *(const float2*)(Ps + r1 * PP + lc);
            float s00 = acc[n][0] * mk0[n].x * scale + p0.x;
            float s01 = acc[n][1] * mk0[n].y * scale + p0.y;
            float s10 = acc[n][2] * mk1[n].x * scale + p1.x;
            float s11 = acc[n][3] * mk1[n].y * scale + p1.y;
            *(float2*)(shh + (size_t)gr0 * SQ + col) = make_float2(s00, s01);
            *(float2*)(shh + (size_t)gr1 * SQ + col) = make_float2(s10, s11);
            float e00 = __expf(s00), e01 = __expf(s01);
            float e10 = __expf(s10), e11 = __expf(s11);
            ls0 += e00 + e01;
            ls1 += e10 + e11;
            *(float2*)(Ps + r0 * PP + lc) = make_float2(e00, e01);  // same-thread overwrite
            *(float2*)(Ps + r1 * PP + lc) = make_float2(e10, e11);
        }
        __syncthreads();   // exp tile complete (cross-warp A-fragments)

        // ---- mma2: out_unnorm += E @ V (per-warp 16x32) ----
        #pragma unroll
        for (int kk = 0; kk < 4; kk++) {
            const int k0 = kk * 8;
            unsigned a[4];
            a[0] = f2tf32(Ps[r0 * PP + k0 + tig]);
            a[1] = f2tf32(Ps[r1 * PP + k0 + tig]);
            a[2] = f2tf32(Ps[r0 * PP + k0 + tig + 4]);
            a[3] = f2tf32(Ps[r1 * PP + k0 + tig + 4]);
            #pragma unroll
            for (int n = 0; n < 4; n++) {
                const int oc = wn * 32 + n * 8 + gID;
                unsigned b[2];
                b[0] = f2tf32(Vs[(k0 + tig) * VP + oc]);
                b[1] = f2tf32(Vs[(k0 + tig + 4) * VP + oc]);
                mma16x8x8(oacc[n], a, b);
            }
        }
        __syncthreads();   // buffer consumers done -> reusable for ch+2 prefetch
    }

    // ---- rowsums -> invs ----
    ls0 += __shfl_xor_sync(0xffffffffu, ls0, 1);
    ls0 += __shfl_xor_sync(0xffffffffu, ls0, 2);
    ls1 += __shfl_xor_sync(0xffffffffu, ls1, 1);
    ls1 += __shfl_xor_sync(0xffffffffu, ls1, 2);
    if (tig == 0) {
        rowsum[wn * 64 + r0] = ls0;
        rowsum[wn * 64 + r1] = ls1;
    }
    __syncthreads();
    if (tid < TQ) invs[tid] = 1.0f / (rowsum[tid] + rowsum[64 + tid]);
    __syncthreads();

    // ---- write output (normalized) ----
    {
        const float inv0 = invs[r0];
        const float inv1 = invs[r1];
        #pragma unroll
        for (int n = 0; n < 4; n++) {
            const int col = wn * 32 + n * 8 + tig * 2;
            *(float2*)(outh + (size_t)gr0 * HD + col) =
                make_float2(oacc[n][0] * inv0, oacc[n][1] * inv0);
            *(float2*)(outh + (size_t)gr1 * HD + col) =
                make_float2(oacc[n][2] * inv1, oacc[n][3] * inv1);
        }
    }

    // ---- weights tail: w = exp(score) * inv (streaming float4) ----
    #pragma unroll 8
    for (int i = tid; i < TQ * (SQ / 4); i += NTHREADS) {
        int r  = i >> 8;
        int c4 = (i & 255) << 2;
        const float iv = invs[r];
        float4 s = *(const float4*)(shh + (size_t)(q0 + r) * SQ + c4);
        float4 w;
        w.x = __expf(s.x) * iv; w.y = __expf(s.y) * iv;
        w.z = __expf(s.z) * iv; w.w = __expf(s.w) * iv;
        *(float4*)(wh + (size_t)(q0 + r) * SQ + c4) = w;
    }
}

extern "C" void kernel_launch(void* const* d_in, const int* in_sizes, int n_in,
                              void* d_out, int out_size) {
    const float* q     = (const float*)d_in[0];
    const float* k     = (const float*)d_in[1];
    const float* v     = (const float*)d_in[2];
    const float* prev  = (const float*)d_in[3];
    const float* mask  = (const float*)d_in[4];
    const float* scale = (const float*)d_in[5];

    float* out = (float*)d_out;
    float* wts = out + (size_t)8 * 16 * 1024 * 64;
    float* scr = wts + (size_t)8 * 16 * 1024 * 1024;

    const size_t smem_bytes = (size_t)SMEM_FLOATS * sizeof(float);   // 75520 B
    cudaFuncSetAttribute(attn_pipe_kernel,
                         cudaFuncAttributeMaxDynamicSharedMemorySize, (int)smem_bytes);

    dim3 grid(SQ / TQ, 8 * 16);   // (16 q-tiles, 128 bh)
    attn_pipe_kernel<<<grid, NTHREADS, smem_bytes>>>(q, k, v, prev, mask, scale,
                                                     out, wts, scr);
}